// round 13
// baseline (speedup 1.0000x reference)
#include <cuda_runtime.h>
#include <cstdint>

// DynamicTopGate, fused kernel, 2x2 warp split (round 13).
//
// Invariants:
//  - NO inline-asm in the GEMM loop (f32x2 asm caps BW at ~1 TB/s).
//  - Scalar fmaf loop, (128,5), unroll-batched loads, <=96 regs: 2.2+ TB/s.
//  - Warp-parallel epilogue costs ~1us (round 12).
// Round-12 exposed L1 at 70% (W1 re-read 4x per 8 rows). This round splits
// work 2x2: each warp does 4 rows x 8 experts, so per 8 rows W1 is read 2x
// and x 2x: 48 LDG.128/chunk vs 72 (0.67x L1 traffic). acc stays 32 regs.
// Cross-warp combine via 512B smem, then round-12's parallel epilogue.

#define IN_DIM 2048
#define NE     16

typedef unsigned long long u64;

__global__ void __launch_bounds__(128, 5)
gate_kernel(const float* __restrict__ x, const float* __restrict__ W1,
            const float* __restrict__ W2, float* __restrict__ out, int B)
{
    __shared__ float hsum[8][NE];     // raw sums for the block's 8 rows

    const int lane = threadIdx.x & 31;
    const int wIn  = threadIdx.x >> 5;       // 0..3
    const int rg   = wIn & 1;                // row group (0: rows 0-3, 1: 4-7)
    const int eg   = wIn >> 1;               // expert group (0: e0-7, 1: e8-15)
    const int brow = blockIdx.x * 8;         // block's first row
    const int row0 = brow + rg * 4;          // this warp's first row

    const float4* xp = reinterpret_cast<const float4*>(x + (size_t)row0 * IN_DIM) + lane;
    const float4* wp = reinterpret_cast<const float4*>(W1 + (size_t)(eg * 8) * IN_DIM) + lane;

    float acc[4][8];
    #pragma unroll
    for (int r = 0; r < 4; ++r)
        #pragma unroll
        for (int e = 0; e < 8; ++e) acc[r][e] = 0.0f;

    // 16 chunks of 128 columns. Unroll 2: 24 LDG.128 batched per body.
    // Plain-C fmaf only -- no asm (protected config).
    #pragma unroll 2
    for (int c = 0; c < IN_DIM / 128; ++c) {
        float4 a[4];
        #pragma unroll
        for (int r = 0; r < 4; ++r)
            a[r] = __ldcs(xp + r * (IN_DIM / 4) + c * 32);   // stream x; L2 backs 2nd reader
        #pragma unroll
        for (int e = 0; e < 8; ++e) {
            float4 w = __ldg(wp + e * (IN_DIM / 4) + c * 32);  // W1 L1-resident
            #pragma unroll
            for (int r = 0; r < 4; ++r)
                acc[r][e] = fmaf(a[r].x, w.x, fmaf(a[r].y, w.y,
                            fmaf(a[r].z, w.z, fmaf(a[r].w, w.w, acc[r][e]))));
        }
    }

    // Butterfly-reduce all 32 accumulators across the warp.
    #pragma unroll
    for (int r = 0; r < 4; ++r)
        #pragma unroll
        for (int e = 0; e < 8; ++e) {
            #pragma unroll
            for (int off = 16; off > 0; off >>= 1)
                acc[r][e] += __shfl_xor_sync(0xffffffffu, acc[r][e], off);
        }

    // Each lane deposits one (row, expert) sum: lane = e*4 + r.
    {
        const int lr = lane & 3;
        const int le_ = lane >> 2;
        float val = 0.0f;
        #pragma unroll
        for (int r = 0; r < 4; ++r)
            #pragma unroll
            for (int e = 0; e < 8; ++e)
                if (lr == r && le_ == e) val = acc[r][e];
        hsum[rg * 4 + lr][eg * 8 + le_] = val;
    }
    __syncthreads();

    // ============ warp-parallel epilogue (round-12 structure) ============
    // Warp wIn handles rows 2*wIn and 2*wIn+1; half-warp hw per row,
    // lane le (0..15) owns expert le.
    const int hw = lane >> 4;
    const int le = lane & 15;
    const int lrow = 2 * wIn + hw;           // block-local row
    const int row  = brow + lrow;
    const unsigned FULL = 0xffffffffu;
    const int hbase = hw << 4;

    float h = tanhf(hsum[lrow][le]);

    // logits[le] = (sum_e h[e] * W2[le, e]) / 0.7 ; gather h via shfl.
    float wr[NE];
    {
        const float4* W2v = reinterpret_cast<const float4*>(W2) + le * (NE / 4);
        #pragma unroll
        for (int q = 0; q < NE / 4; ++q) {
            float4 w = __ldg(W2v + q);
            wr[4 * q + 0] = w.x; wr[4 * q + 1] = w.y;
            wr[4 * q + 2] = w.z; wr[4 * q + 3] = w.w;
        }
    }
    float logit = 0.0f;
    #pragma unroll
    for (int e = 0; e < NE; ++e) {
        float he = __shfl_sync(FULL, h, hbase + e);
        logit = fmaf(he, wr[e], logit);
    }
    float v = logit / 0.7f;

    // Pack sort key: monotone float high, (15-idx) low -> stable descending.
    unsigned iv = __float_as_uint(v);
    unsigned mk = iv ^ (unsigned)(((int)iv >> 31) | 0x80000000);
    u64 key = ((u64)mk << 32) | (unsigned)(15 - le);

    // Bitonic sort, descending, 16 lanes per half-warp.
    #pragma unroll
    for (int k2 = 2; k2 <= 16; k2 <<= 1) {
        #pragma unroll
        for (int j = k2 >> 1; j > 0; j >>= 1) {
            u64 other = __shfl_xor_sync(FULL, key, j);
            bool lowlane = ((le & j) == 0);
            bool dirup   = ((le & k2) == 0);
            bool wantMax = (lowlane == dirup);
            bool take = wantMax ? (other > key) : (other < key);
            if (take) key = other;
        }
    }

    int sidx = 15 - (int)(key & 0xFu);
    unsigned smk = (unsigned)(key >> 32);
    unsigned siv = (smk & 0x80000000u) ? (smk ^ 0x80000000u) : ~smk;
    float sval = __uint_as_float(siv);

    // Softmax over sorted logits (max at lane hbase).
    float m = __shfl_sync(FULL, sval, hbase);
    float p = expf(sval - m);
    float ssum = p;
    #pragma unroll
    for (int off = 8; off > 0; off >>= 1)
        ssum += __shfl_xor_sync(FULL, ssum, off);
    p *= (1.0f / ssum);

    // Inclusive cumsum within half-warp.
    float cum = p;
    #pragma unroll
    for (int off = 1; off < 16; off <<= 1) {
        float t = __shfl_up_sync(FULL, cum, off);
        if (le >= off) cum += t;
    }

    // k = first position where cum >= 0.92 (else 16).
    unsigned bal = __ballot_sync(FULL, cum >= 0.92f);
    unsigned half_mask = (bal >> (hw << 4)) & 0xFFFFu;
    int k = half_mask ? __ffs(half_mask) : NE;

    float p1 = __shfl_sync(FULL, p, hbase + 0);
    float p2 = __shfl_sync(FULL, p, hbase + 1);
    float p3 = __shfl_sync(FULL, p, hbase + 2);
    if (p1 >= 0.46f && (p1 - p2) >= 0.1f) k = 1;
    if (k > 2 && ((p1 + p2) >= 0.82f || p3 <= 0.12f || (p2 - p3) <= 0.03f)) k = 2;
    if (k < 1) k = 1;
    if (k > 3) k = 3;

    float* oidx  = out;
    float* osc   = out + (size_t)B * 8;
    float* omask = out + (size_t)B * 16;
    float* okv   = out + (size_t)B * 24;
    if (le < 8) {
        float msk = (le < k) ? 1.0f : 0.0f;
        oidx[row * 8 + le]  = (float)sidx;
        osc[row * 8 + le]   = p * msk;
        omask[row * 8 + le] = msk;
        if (le == 0) okv[row] = (float)k;
    }
}

extern "C" void kernel_launch(void* const* d_in, const int* in_sizes, int n_in,
                              void* d_out, int out_size)
{
    const float* x  = (const float*)d_in[0];
    const float* W1 = (const float*)d_in[1];
    const float* W2 = (const float*)d_in[2];
    float* out = (float*)d_out;

    int B = in_sizes[0] / IN_DIM;                 // 16384

    // 4 warps/block, 8 rows/block (2x2 row/expert split).
    int blocks = (B + 7) / 8;                     // 2048
    gate_kernel<<<blocks, 128>>>(x, W1, W2, out, B);
}

// round 15
// speedup vs baseline: 1.2896x; 1.2896x over previous
#include <cuda_runtime.h>
#include <cstdint>

// DynamicTopGate, fused kernel, 3 rows/warp (round 14).
//
// Invariants:
//  - NO inline-asm in the GEMM loop (caps BW at ~1 TB/s).
//  - Scalar fmaf loop, (128,5), batched __ldcs x-loads / __ldg W1, <=96 regs.
//  - Warp-parallel epilogue (round 12) costs ~1us.
//  - No cross-warp data duplication (round-13 lesson: __ldcs double-read
//    of x stalls the second reader; reg pressure from a[4] kills batching).
// This round: 3 rows/warp, all 16 experts per warp. W1 L1-wavefronts per row
// drop 32 -> 21.3 (L1 time ~36 -> ~25us), FMA (~32us) becomes the bound.

#define IN_DIM 2048
#define NE     16

typedef unsigned long long u64;

__global__ void __launch_bounds__(128, 5)
gate_kernel(const float* __restrict__ x, const float* __restrict__ W1,
            const float* __restrict__ W2, float* __restrict__ out, int B)
{
    __shared__ float hsum[12][NE];    // raw GEMM1 sums for the block's 12 rows

    const int lane = threadIdx.x & 31;
    const int wIn  = threadIdx.x >> 5;         // 0..3
    const int brow = blockIdx.x * 12;
    const int row0 = brow + wIn * 3;           // this warp's first row

    // Clamp row indices for loads (last block): duplicate work, discarded.
    const int r0 = row0     < B ? row0     : B - 1;
    const int r1 = row0 + 1 < B ? row0 + 1 : B - 1;
    const int r2 = row0 + 2 < B ? row0 + 2 : B - 1;

    const float4* x0 = reinterpret_cast<const float4*>(x + (size_t)r0 * IN_DIM) + lane;
    const float4* x1 = reinterpret_cast<const float4*>(x + (size_t)r1 * IN_DIM) + lane;
    const float4* x2 = reinterpret_cast<const float4*>(x + (size_t)r2 * IN_DIM) + lane;
    const float4* wp = reinterpret_cast<const float4*>(W1) + lane;

    float acc0[NE], acc1[NE], acc2[NE];
    #pragma unroll
    for (int e = 0; e < NE; ++e) { acc0[e] = 0.0f; acc1[e] = 0.0f; acc2[e] = 0.0f; }

    // 16 chunks of 128 columns; unroll 2 -> 6 batched x LDG.128 per body.
    // Plain-C fmaf only -- no asm (protected config).
    #pragma unroll 2
    for (int c = 0; c < IN_DIM / 128; ++c) {
        float4 a0 = __ldcs(x0 + c * 32);       // stream x: keep W1 in L1
        float4 a1 = __ldcs(x1 + c * 32);
        float4 a2 = __ldcs(x2 + c * 32);
        #pragma unroll
        for (int e = 0; e < NE; ++e) {
            float4 w = __ldg(wp + e * (IN_DIM / 4) + c * 32);   // W1 L1-resident
            acc0[e] = fmaf(a0.x, w.x, fmaf(a0.y, w.y,
                      fmaf(a0.z, w.z, fmaf(a0.w, w.w, acc0[e]))));
            acc1[e] = fmaf(a1.x, w.x, fmaf(a1.y, w.y,
                      fmaf(a1.z, w.z, fmaf(a1.w, w.w, acc1[e]))));
            acc2[e] = fmaf(a2.x, w.x, fmaf(a2.y, w.y,
                      fmaf(a2.z, w.z, fmaf(a2.w, w.w, acc2[e]))));
        }
    }

    // Butterfly-reduce all accumulators across the warp.
    #pragma unroll
    for (int e = 0; e < NE; ++e) {
        #pragma unroll
        for (int off = 16; off > 0; off >>= 1) {
            acc0[e] += __shfl_xor_sync(0xffffffffu, acc0[e], off);
            acc1[e] += __shfl_xor_sync(0xffffffffu, acc1[e], off);
            acc2[e] += __shfl_xor_sync(0xffffffffu, acc2[e], off);
        }
    }

    // Deposit: rows 0,1 by all 32 lanes (lane = r*16+e), row 2 by lanes 0-15.
    {
        const int dr = lane >> 4;          // 0 or 1
        const int de = lane & 15;
        float val = 0.0f;
        #pragma unroll
        for (int e = 0; e < NE; ++e)
            if (de == e) val = dr ? acc1[e] : acc0[e];
        hsum[wIn * 3 + dr][de] = val;
        if (lane < 16) {
            float v2 = 0.0f;
            #pragma unroll
            for (int e = 0; e < NE; ++e)
                if (lane == e) v2 = acc2[e];
            hsum[wIn * 3 + 2][lane] = v2;
        }
    }
    __syncthreads();

    // ============ warp-parallel epilogue (round-12 structure) ============
    // Pass 1: warps 0-3 handle block rows 0-7; pass 2: warps 0-1 rows 8-11.
    const int hw = lane >> 4;
    const int le = lane & 15;
    const unsigned FULL = 0xffffffffu;
    const int hbase = hw << 4;

    float wr[NE];
    {
        const float4* W2v = reinterpret_cast<const float4*>(W2) + le * (NE / 4);
        #pragma unroll
        for (int q = 0; q < NE / 4; ++q) {
            float4 w = __ldg(W2v + q);
            wr[4 * q + 0] = w.x; wr[4 * q + 1] = w.y;
            wr[4 * q + 2] = w.z; wr[4 * q + 3] = w.w;
        }
    }

    float* oidx  = out;
    float* osc   = out + (size_t)B * 8;
    float* omask = out + (size_t)B * 16;
    float* okv   = out + (size_t)B * 24;

    #pragma unroll
    for (int pass = 0; pass < 2; ++pass) {
        const int lrow = pass == 0 ? (2 * wIn + hw) : (8 + 2 * wIn + hw);
        const int row  = brow + lrow;
        if (pass == 1 && wIn >= 2) break;   // only warps 0-1 in pass 2
        if (row >= B) continue;

        float h = tanhf(hsum[lrow][le]);

        // logits[le] = (sum_e h[e] * W2[le, e]) / 0.7 ; gather h via shfl.
        float logit = 0.0f;
        #pragma unroll
        for (int e = 0; e < NE; ++e) {
            float he = __shfl_sync(FULL, h, hbase + e);
            logit = fmaf(he, wr[e], logit);
        }
        float v = logit / 0.7f;

        // Pack key: monotone float high, (15-idx) low -> stable descending.
        unsigned iv = __float_as_uint(v);
        unsigned mk = iv ^ (unsigned)(((int)iv >> 31) | 0x80000000);
        u64 key = ((u64)mk << 32) | (unsigned)(15 - le);

        // Bitonic sort, descending, 16 lanes per half-warp.
        #pragma unroll
        for (int k2 = 2; k2 <= 16; k2 <<= 1) {
            #pragma unroll
            for (int j = k2 >> 1; j > 0; j >>= 1) {
                u64 other = __shfl_xor_sync(FULL, key, j);
                bool lowlane = ((le & j) == 0);
                bool dirup   = ((le & k2) == 0);
                bool wantMax = (lowlane == dirup);
                bool take = wantMax ? (other > key) : (other < key);
                if (take) key = other;
            }
        }

        int sidx = 15 - (int)(key & 0xFu);
        unsigned smk = (unsigned)(key >> 32);
        unsigned siv = (smk & 0x80000000u) ? (smk ^ 0x80000000u) : ~smk;
        float sval = __uint_as_float(siv);

        // Softmax over sorted logits (max at lane hbase).
        float m = __shfl_sync(FULL, sval, hbase);
        float p = expf(sval - m);
        float ssum = p;
        #pragma unroll
        for (int off = 8; off > 0; off >>= 1)
            ssum += __shfl_xor_sync(FULL, ssum, off);
        p *= (1.0f / ssum);

        // Inclusive cumsum within half-warp.
        float cum = p;
        #pragma unroll
        for (int off = 1; off < 16; off <<= 1) {
            float t = __shfl_up_sync(FULL, cum, off);
            if (le >= off) cum += t;
        }

        // k = first position where cum >= 0.92 (else 16).
        unsigned bal = __ballot_sync(FULL, cum >= 0.92f);
        unsigned half_mask = (bal >> hbase) & 0xFFFFu;
        int k = half_mask ? __ffs(half_mask) : NE;

        float p1 = __shfl_sync(FULL, p, hbase + 0);
        float p2 = __shfl_sync(FULL, p, hbase + 1);
        float p3 = __shfl_sync(FULL, p, hbase + 2);
        if (p1 >= 0.46f && (p1 - p2) >= 0.1f) k = 1;
        if (k > 2 && ((p1 + p2) >= 0.82f || p3 <= 0.12f || (p2 - p3) <= 0.03f)) k = 2;
        if (k < 1) k = 1;
        if (k > 3) k = 3;

        if (le < 8) {
            float msk = (le < k) ? 1.0f : 0.0f;
            oidx[row * 8 + le]  = (float)sidx;
            osc[row * 8 + le]   = p * msk;
            omask[row * 8 + le] = msk;
            if (le == 0) okv[row] = (float)k;
        }
    }
}

extern "C" void kernel_launch(void* const* d_in, const int* in_sizes, int n_in,
                              void* d_out, int out_size)
{
    const float* x  = (const float*)d_in[0];
    const float* W1 = (const float*)d_in[1];
    const float* W2 = (const float*)d_in[2];
    float* out = (float*)d_out;

    int B = in_sizes[0] / IN_DIM;                 // 16384

    // 4 warps/block, 3 rows/warp -> 12 rows/block.
    int blocks = (B + 11) / 12;                   // 1366
    gate_kernel<<<blocks, 128>>>(x, W1, W2, out, B);
}